// round 17
// baseline (speedup 1.0000x reference)
#include <cuda_runtime.h>
#include <math.h>

// Problem shape (fixed by reference)
#define BB 32
#define TT 2048
#define HE 1024
#define DEC_FLAT 2048

// 444 CTAs = 148 SMs x occ 3, exactly one wave, every SM gets 3 CTAs.
// 444 x 8 = 3552 warps = 32 batches x 111 warps, exactly.
#define GRID_MAIN 444
#define WPB 8
#define TW (GRID_MAIN * WPB)   // 3552 warps
#define WB (TW / BB)           // 111 warps per batch

// Scratch: __device__ globals (no allocation allowed)
__device__ float g_ps[TW];
__device__ float g_pacc[(size_t)TW * HE];   // 14.2 MB
__device__ int   g_cnt[BB];                 // zero-init; reset by reducer

// ---------------------------------------------------------------------------
// Fully fused kernel (no online max: energies are bounded |e| < ~7 and a
// constant offset cancels exactly in the normalization, so plain exp is safe
// and partial combination is a pure sum):
//   phase 0: w_e -> shared; per-block cooperative bias for 1-2 batches
//   phase 1: per-warp exp-weighted accumulation, ONE row per iteration,
//            rows wb + k*111 within the warp's batch (18-19 rows)
//   phase 2: CTA whose warps complete a batch (count hits 111) reduces it
// Occupancy 3 (<=85 regs) is the point: w_e lives in shared, not registers.
// ---------------------------------------------------------------------------
__global__ __launch_bounds__(256, 3)
void attn_fused_kernel(const float* __restrict__ hidden,
                       const float* __restrict__ enc,
                       const float* __restrict__ mask,
                       const float* __restrict__ attn_w,
                       const float* __restrict__ attn_b,
                       float* __restrict__ out) {
    const int tid  = threadIdx.x;
    const int lane = tid & 31;
    const int wid  = tid >> 5;
    const int g    = blockIdx.x * WPB + wid;     // global warp id
    const int b    = g / WB;                     // this warp's batch
    const int wb   = g % WB;                     // warp index within batch
    const int b_lo = (blockIdx.x * WPB) / WB;
    const int b_hi = (blockIdx.x * WPB + WPB - 1) / WB;

    __shared__ float sh_we[HE];                  // w_e staged per CTA (4 KB)
    __shared__ float sh[WPB];
    __shared__ float s_bias[2];
    __shared__ int   s_do[2];
    __shared__ float s_invS;

    // stage w_e into shared
    for (int j = tid; j < HE; j += 256) sh_we[j] = attn_w[DEC_FLAT + j];

    // ---- phase 0: biases for b_lo (threads 0-127) and b_hi (128-255) ----
    {
        const int ht = tid & 127;
        const int hb = (tid >> 7) ? b_hi : b_lo;
        float sum = 0.f;
        const float* h0 = hidden + (size_t)hb * HE;        // hidden[0, hb, :]
        const float* h1 = hidden + (size_t)(BB + hb) * HE; // hidden[1, hb, :]
#pragma unroll
        for (int j = ht; j < HE; j += 128)
            sum += h0[j] * attn_w[j] + h1[j] * attn_w[HE + j];
#pragma unroll
        for (int off = 16; off > 0; off >>= 1)
            sum += __shfl_xor_sync(0xffffffffu, sum, off);
        if (lane == 0) sh[wid] = sum;
        __syncthreads();
        if (tid == 0)   s_bias[0] = sh[0] + sh[1] + sh[2] + sh[3] + attn_b[0];
        if (tid == 128) s_bias[1] = sh[4] + sh[5] + sh[6] + sh[7] + attn_b[0];
        __syncthreads();
    }
    const float bias = s_bias[(b == b_lo) ? 0 : 1];

    // ---- phase 1: rows wb + k*111, one per iteration ----
    const int nrows = (TT - wb + WB - 1) / WB;   // 18 or 19
    float mymask = 0.f;                          // lane k holds row-k's mask
    if (lane < nrows)
        mymask = mask[(size_t)b * TT + wb + (size_t)lane * WB];

    float4 av[8];
#pragma unroll
    for (int i = 0; i < 8; i++) av[i] = make_float4(0.f, 0.f, 0.f, 0.f);
    float s = 0.f;

    const float* encb = enc + (size_t)b * TT * HE;
    const float* wep  = sh_we + lane * 4;        // lane's float4 column base

    for (int k = 0; k < nrows; k++) {
        const size_t row = (size_t)wb + (size_t)k * WB;
        const float4* rowp = (const float4*)(encb + row * HE);
        float4 rv[8];
#pragma unroll
        for (int i = 0; i < 8; i++) rv[i] = rowp[i * 32 + lane]; // MLP=8

        // 4-accumulator dot; w_e from shared (no register copy)
        float d0 = 0.f, d1 = 0.f, d2 = 0.f, d3 = 0.f;
#pragma unroll
        for (int i = 0; i < 8; i += 4) {
            float4 w0 = *(const float4*)(wep + (i + 0) * 128);
            float4 w1 = *(const float4*)(wep + (i + 1) * 128);
            float4 w2 = *(const float4*)(wep + (i + 2) * 128);
            float4 w3 = *(const float4*)(wep + (i + 3) * 128);
            d0 = fmaf(rv[i+0].x, w0.x, d0);
            d0 = fmaf(rv[i+0].y, w0.y, d0);
            d0 = fmaf(rv[i+0].z, w0.z, d0);
            d0 = fmaf(rv[i+0].w, w0.w, d0);
            d1 = fmaf(rv[i+1].x, w1.x, d1);
            d1 = fmaf(rv[i+1].y, w1.y, d1);
            d1 = fmaf(rv[i+1].z, w1.z, d1);
            d1 = fmaf(rv[i+1].w, w1.w, d1);
            d2 = fmaf(rv[i+2].x, w2.x, d2);
            d2 = fmaf(rv[i+2].y, w2.y, d2);
            d2 = fmaf(rv[i+2].z, w2.z, d2);
            d2 = fmaf(rv[i+2].w, w2.w, d2);
            d3 = fmaf(rv[i+3].x, w3.x, d3);
            d3 = fmaf(rv[i+3].y, w3.y, d3);
            d3 = fmaf(rv[i+3].z, w3.z, d3);
            d3 = fmaf(rv[i+3].w, w3.w, d3);
        }
        float d = (d0 + d1) + (d2 + d3);
#pragma unroll
        for (int off = 16; off > 0; off >>= 1)
            d += __shfl_xor_sync(0xffffffffu, d, off);

        const float mk = __shfl_sync(0xffffffffu, mymask, k);
        const float p = __expf((d + bias) * mk) * mk;
        s += p;
#pragma unroll
        for (int i = 0; i < 8; i++) {
            av[i].x = fmaf(p, rv[i].x, av[i].x);
            av[i].y = fmaf(p, rv[i].y, av[i].y);
            av[i].z = fmaf(p, rv[i].z, av[i].z);
            av[i].w = fmaf(p, rv[i].w, av[i].w);
        }
    }

    if (lane == 0) g_ps[g] = s;
    float4* outp = (float4*)(g_pacc + (size_t)g * HE);
#pragma unroll
    for (int i = 0; i < 8; i++) outp[i * 32 + lane] = av[i];

    // ---- phase 2: last CTA to complete a batch reduces its 111 partials ----
    __threadfence();                        // publish partials before arrival
    __syncthreads();                        // all warps' stores issued
    if (tid == 0) {
        const int cw0 = min((b_lo + 1) * WB, blockIdx.x * WPB + WPB)
                      - blockIdx.x * WPB;   // warps contributed to b_lo
        const int cw1 = WPB - cw0;          // warps contributed to b_hi
        s_do[0] = (atomicAdd(&g_cnt[b_lo], cw0) + cw0 == WB);
        s_do[1] = 0;
        if (cw1 > 0)
            s_do[1] = (atomicAdd(&g_cnt[b_hi], cw1) + cw1 == WB);
    }
    __syncthreads();

    for (int q = 0; q < 2; q++) {
        if (!s_do[q]) continue;
        const int rb = q ? b_hi : b_lo;
        __threadfence();                    // acquire side of the handoff

        // S = plain sum of the 111 partial sums
        float v = (tid < WB) ? g_ps[rb * WB + tid] : 0.f;
#pragma unroll
        for (int off = 16; off > 0; off >>= 1)
            v += __shfl_xor_sync(0xffffffffu, v, off);
        if (lane == 0) sh[wid] = v;
        __syncthreads();
        if (tid == 0) {
            float S = 0.f;
#pragma unroll
            for (int w = 0; w < WPB; w++) S += sh[w];
            s_invS = 1.f / S;
            g_cnt[rb] = 0;                  // reset for next graph replay
        }
        __syncthreads();
        const float inv = s_invS;

        // thread tid owns cols [tid*4, tid*4+4): pure sum over 111 partials
        float4 acc = make_float4(0.f, 0.f, 0.f, 0.f);
        const float* base = g_pacc + (size_t)rb * WB * HE + tid * 4;
#pragma unroll 2
        for (int p = 0; p < WB; p++) {
            float4 vv = *(const float4*)(base + (size_t)p * HE);
            acc.x += vv.x; acc.y += vv.y; acc.z += vv.z; acc.w += vv.w;
        }
        *(float4*)(out + (size_t)rb * HE + tid * 4) =
            make_float4(acc.x * inv, acc.y * inv, acc.z * inv, acc.w * inv);
        __syncthreads();                    // shared reuse safety across q
    }
}

// ---------------------------------------------------------------------------
// Entry point. Inputs (metadata order): hidden, encoder_outputs, mask,
// attn_w, attn_b. Output: (32, 1024) f32.
// ---------------------------------------------------------------------------
extern "C" void kernel_launch(void* const* d_in, const int* in_sizes, int n_in,
                              void* d_out, int out_size) {
    const float* hidden = (const float*)d_in[0];
    const float* enc    = (const float*)d_in[1];
    const float* mask   = (const float*)d_in[2];
    const float* attn_w = (const float*)d_in[3];
    const float* attn_b = (const float*)d_in[4];
    float* out = (float*)d_out;

    attn_fused_kernel<<<GRID_MAIN, 256>>>(hidden, enc, mask, attn_w, attn_b, out);
}